// round 1
// baseline (speedup 1.0000x reference)
#include <cuda_runtime.h>
#include <cuda_bf16.h>
#include <math.h>

#define NU 40000
#define NI 40000
#define NN 40000
#define C 128
#define H 4
#define HD 32
#define E 200000
#define HSIZE (1 << 19)
#define HMASK (HSIZE - 1)

// ---------------- device scratch (static, no allocs) ----------------
__device__ int   g_ht_keys[4 * HSIZE];
__device__ int   g_ht_cnt [4 * HSIZE];
__device__ float g_proj[6 * NN * C];     // 0:Qu 1:Ku 2:Vu 3:Qi 4:Ki 5:Vi
__device__ float g_agg [2 * NN * C];     // weighted-V aggregate per relation
__device__ float g_score[2 * E * H];     // raw scores, then exp values
__device__ unsigned g_mx[2 * NN * H];    // encoded running max
__device__ float g_z [2 * NN * H];       // softmax denominators
__device__ int g_cnt_su[NN], g_cnt_du[NN], g_cnt_si[NN], g_cnt_di[NN];

// ---------------- helpers ----------------
__device__ __forceinline__ unsigned hash_key(int key) {
    unsigned h = (unsigned)key * 2654435761u;
    h ^= h >> 15;
    return h & HMASK;
}

__device__ __forceinline__ void ht_insert(int t, int key) {
    unsigned slot = hash_key(key);
    int* keys = g_ht_keys + t * HSIZE;
    int* cnts = g_ht_cnt + t * HSIZE;
    while (true) {
        int k = keys[slot];
        if (k == key) { atomicAdd(&cnts[slot], 1); return; }
        if (k == -1) {
            int old = atomicCAS(&keys[slot], -1, key);
            if (old == -1 || old == key) { atomicAdd(&cnts[slot], 1); return; }
        }
        slot = (slot + 1) & HMASK;
    }
}

__device__ __forceinline__ int ht_query(int t, int key) {
    unsigned slot = hash_key(key);
    const int* keys = g_ht_keys + t * HSIZE;
    const int* cnts = g_ht_cnt + t * HSIZE;
    while (true) {
        int k = keys[slot];
        if (k == key) return cnts[slot];
        if (k == -1) return 0;
        slot = (slot + 1) & HMASK;
    }
}

// order-preserving float -> uint encoding for atomicMax
__device__ __forceinline__ unsigned fenc(float f) {
    unsigned u = __float_as_uint(f);
    return (u & 0x80000000u) ? ~u : (u | 0x80000000u);
}
__device__ __forceinline__ float fdec(unsigned u) {
    unsigned v = (u & 0x80000000u) ? (u & 0x7FFFFFFFu) : ~u;
    return __uint_as_float(v);
}

// ---------------- kernels ----------------
__global__ void clear_kernel() {
    int gid = blockIdx.x * blockDim.x + threadIdx.x;
    int T = gridDim.x * blockDim.x;
    for (int i = gid; i < 4 * HSIZE; i += T) { g_ht_keys[i] = -1; g_ht_cnt[i] = 0; }
    for (int i = gid; i < 2 * NN * H; i += T) { g_mx[i] = 0u; g_z[i] = 0.f; }
    for (int i = gid; i < 2 * NN * C; i += T) g_agg[i] = 0.f;
    for (int i = gid; i < NN; i += T) {
        g_cnt_su[i] = 0; g_cnt_du[i] = 0; g_cnt_si[i] = 0; g_cnt_di[i] = 0;
    }
}

__global__ void build_ht_kernel(const int* __restrict__ eui, const int* __restrict__ eiu) {
    int e = blockIdx.x * blockDim.x + threadIdx.x;
    if (e >= 2 * E) return;
    if (e < E) {
        int su = eui[e], du = eui[e + E];
        ht_insert(0, su * NI + du);      // pid_ui multiset
        ht_insert(3, du * NU + su);      // rev pairs for iu relation
        atomicAdd(&g_cnt_su[su], 1);
        atomicAdd(&g_cnt_du[du], 1);
    } else {
        int i = e - E;
        int si = eiu[i], di = eiu[i + E];
        ht_insert(1, si * NU + di);      // pid_iu multiset
        ht_insert(2, di * NI + si);      // rev pairs for ui relation
        atomicAdd(&g_cnt_si[si], 1);
        atomicAdd(&g_cnt_di[di], 1);
    }
}

// C[m][n] = sum_k A[m][k] * W[n][k] (+ bias[n]) ; M rows, K=N=128
#define GEMM_SMEM ((128 * 128 + 128 * 129) * 4)
__global__ void gemm128_kernel(const float* __restrict__ A, int M,
                               const float* __restrict__ W,
                               const float* __restrict__ bias,
                               float* __restrict__ Cout) {
    extern __shared__ float sh[];
    float* As = sh;             // [128][128]
    float* Ws = sh + 128 * 128; // [128][129] transposed (k-major)
    int tid = threadIdx.x;
    int row0 = blockIdx.x * 128;

    for (int i = tid; i < 128 * 32; i += 256) {
        int r = i >> 5, c4 = (i & 31) << 2;
        float4 v = make_float4(0.f, 0.f, 0.f, 0.f);
        if (row0 + r < M) v = *(const float4*)(A + (size_t)(row0 + r) * 128 + c4);
        *(float4*)(As + r * 128 + c4) = v;
    }
    for (int i = tid; i < 128 * 32; i += 256) {
        int n = i >> 5, k4 = (i & 31) << 2;
        float4 v = *(const float4*)(W + n * 128 + k4);
        Ws[(k4 + 0) * 129 + n] = v.x;
        Ws[(k4 + 1) * 129 + n] = v.y;
        Ws[(k4 + 2) * 129 + n] = v.z;
        Ws[(k4 + 3) * 129 + n] = v.w;
    }
    __syncthreads();

    int tx = tid & 15, ty = tid >> 4;
    float acc[8][8];
    #pragma unroll
    for (int i = 0; i < 8; i++)
        #pragma unroll
        for (int j = 0; j < 8; j++) acc[i][j] = 0.f;

    #pragma unroll 16
    for (int k = 0; k < 128; k++) {
        float a[8], w[8];
        #pragma unroll
        for (int i = 0; i < 8; i++) a[i] = As[(ty * 8 + i) * 128 + k];
        #pragma unroll
        for (int j = 0; j < 8; j++) w[j] = Ws[k * 129 + tx * 8 + j];
        #pragma unroll
        for (int i = 0; i < 8; i++)
            #pragma unroll
            for (int j = 0; j < 8; j++) acc[i][j] = fmaf(a[i], w[j], acc[i][j]);
    }

    float b0[8] = {0, 0, 0, 0, 0, 0, 0, 0};
    if (bias) {
        #pragma unroll
        for (int j = 0; j < 8; j++) b0[j] = bias[tx * 8 + j];
    }
    #pragma unroll
    for (int i = 0; i < 8; i++) {
        int r = row0 + ty * 8 + i;
        if (r >= M) continue;
        float4 o0 = make_float4(acc[i][0] + b0[0], acc[i][1] + b0[1],
                                acc[i][2] + b0[2], acc[i][3] + b0[3]);
        float4 o1 = make_float4(acc[i][4] + b0[4], acc[i][5] + b0[5],
                                acc[i][6] + b0[6], acc[i][7] + b0[7]);
        *(float4*)(Cout + (size_t)r * 128 + tx * 8)     = o0;
        *(float4*)(Cout + (size_t)r * 128 + tx * 8 + 4) = o1;
    }
}

// pass A: scores + per-(dst,head) running max. one warp per edge.
__global__ void score_kernel(const int* __restrict__ eui, const int* __restrict__ eiu,
                             const float* __restrict__ t_user, const float* __restrict__ t_item,
                             const float* __restrict__ hb, const float* __restrict__ beta,
                             const float* __restrict__ tau_raw,
                             const float* __restrict__ gamma, const float* __restrict__ delta) {
    int wg = (blockIdx.x * blockDim.x + threadIdx.x) >> 5;
    int lane = threadIdx.x & 31;
    int r = blockIdx.y;
    if (wg >= E) return;
    int e = wg;
    const int* ei = r ? eiu : eui;
    int src = ei[e], dst = ei[e + E];
    const float* Q = g_proj + (size_t)(r == 0 ? 3 : 0) * NN * C + (size_t)dst * C;
    const float* K = g_proj + (size_t)(r == 0 ? 1 : 4) * NN * C + (size_t)src * C;
    float4 q = *(const float4*)(Q + lane * 4);
    float4 k = *(const float4*)(K + lane * 4);
    float p = q.x * k.x + q.y * k.y + q.z * k.z + q.w * k.w;
    p += __shfl_xor_sync(0xffffffffu, p, 1);
    p += __shfl_xor_sync(0xffffffffu, p, 2);
    p += __shfl_xor_sync(0xffffffffu, p, 4);

    float dtc = 0.f, cntf = 0.f, recf = 0.f;
    if (lane == 0) {
        float ts = (r == 0 ? t_user : t_item)[src];
        float td = (r == 0 ? t_item : t_user)[dst];
        dtc = fabsf(td - ts) + 1e-6f;
        int pid = src * 40000 + dst;
        cntf = (float)(ht_query(r, pid) - 1);
        recf = (ht_query(2 + r, pid) > 0) ? 1.f : 0.f;
    }
    dtc  = __shfl_sync(0xffffffffu, dtc, 0);
    cntf = __shfl_sync(0xffffffffu, cntf, 0);
    recf = __shfl_sync(0xffffffffu, recf, 0);

    if ((lane & 7) == 0) {
        int h = lane >> 3;
        float tr = tau_raw[r];
        float tau = log1pf(expf(tr)) + 1e-6f;
        float s = p * 0.1767766952966369f + hb[r * H + h]
                - log1pf(dtc / tau) * beta[r * H + h]
                + log1pf(cntf) * gamma[r * H + h]
                + recf * delta[r * H + h];
        g_score[(size_t)r * E * H + (size_t)e * H + h] = s;
        atomicMax(&g_mx[r * NN * H + dst * H + h], fenc(s));
    }
}

// pass B: exp(s - max), accumulate denominators. one thread per (edge, head).
__global__ void expsum_kernel(const int* __restrict__ eui, const int* __restrict__ eiu) {
    int idx = blockIdx.x * blockDim.x + threadIdx.x;
    if (idx >= E * H) return;
    int r = blockIdx.y;
    int e = idx >> 2, h = idx & 3;
    const int* ei = r ? eiu : eui;
    int dst = ei[e + E];
    float m = fdec(g_mx[r * NN * H + dst * H + h]);
    float ex = expf(g_score[(size_t)r * E * H + idx] - m);
    g_score[(size_t)r * E * H + idx] = ex;
    atomicAdd(&g_z[r * NN * H + dst * H + h], ex);
}

// pass C: w = exp/z, scatter-add w*V into per-dst aggregate. one warp per edge.
__global__ void aggregate_kernel(const int* __restrict__ eui, const int* __restrict__ eiu) {
    int wg = (blockIdx.x * blockDim.x + threadIdx.x) >> 5;
    int lane = threadIdx.x & 31;
    int r = blockIdx.y;
    if (wg >= E) return;
    int e = wg;
    const int* ei = r ? eiu : eui;
    int src = ei[e], dst = ei[e + E];
    int h = lane >> 3;
    float w = g_score[(size_t)r * E * H + (size_t)e * H + h]
            / g_z[r * NN * H + dst * H + h];
    const float* V = g_proj + (size_t)(r == 0 ? 2 : 5) * NN * C + (size_t)src * C;
    float4 v = *(const float4*)(V + lane * 4);
    float* ag = g_agg + (size_t)r * NN * C + (size_t)dst * C + lane * 4;
    atomicAdd(ag + 0, v.x * w);
    atomicAdd(ag + 1, v.y * w);
    atomicAdd(ag + 2, v.z * w);
    atomicAdd(ag + 3, v.w * w);
}

// final: out = LayerNorm(proj + indeg*bo + deg + x). one warp per node.
__global__ void final_kernel(const float* __restrict__ x_user, const float* __restrict__ x_item,
                             const float* __restrict__ bo, float* __restrict__ out) {
    int n = (blockIdx.x * blockDim.x + threadIdx.x) >> 5;
    int lane = threadIdx.x & 31;
    int ty = blockIdx.y;     // 0 = user, 1 = item
    if (n >= NN) return;
    float* o = out + (ty == 0 ? (size_t)0 : (size_t)NN * C) + (size_t)n * C;
    const float* x = (ty == 0 ? x_user : x_item) + (size_t)n * C;
    float indeg = (float)(ty == 0 ? g_cnt_di[n] : g_cnt_du[n]);
    float deg = (float)(ty == 0 ? (g_cnt_su[n] + g_cnt_di[n])
                                : (g_cnt_du[n] + g_cnt_si[n]));
    float4 v  = *(float4*)(o + lane * 4);
    float4 xv = *(const float4*)(x + lane * 4);
    float4 bv = *(const float4*)(bo + lane * 4);
    v.x += xv.x + indeg * bv.x + deg;
    v.y += xv.y + indeg * bv.y + deg;
    v.z += xv.z + indeg * bv.z + deg;
    v.w += xv.w + indeg * bv.w + deg;
    float s = v.x + v.y + v.z + v.w;
    #pragma unroll
    for (int d = 16; d; d >>= 1) s += __shfl_xor_sync(0xffffffffu, s, d);
    float mu = s * (1.f / 128.f);
    float d0 = v.x - mu, d1 = v.y - mu, d2 = v.z - mu, d3 = v.w - mu;
    float q = d0 * d0 + d1 * d1 + d2 * d2 + d3 * d3;
    #pragma unroll
    for (int d = 16; d; d >>= 1) q += __shfl_xor_sync(0xffffffffu, q, d);
    float inv = 1.f / sqrtf(q * (1.f / 128.f) + 1e-5f);
    float4 r4 = make_float4(d0 * inv, d1 * inv, d2 * inv, d3 * inv);
    *(float4*)(o + lane * 4) = r4;
}

// ---------------- launch ----------------
extern "C" void kernel_launch(void* const* d_in, const int* in_sizes, int n_in,
                              void* d_out, int out_size) {
    const float* x_user  = (const float*)d_in[0];
    const float* x_item  = (const float*)d_in[1];
    const float* t_user  = (const float*)d_in[2];
    const float* t_item  = (const float*)d_in[3];
    const int*   eui     = (const int*)d_in[4];
    const int*   eiu     = (const int*)d_in[5];
    const float* Wq      = (const float*)d_in[6];
    const float* bq      = (const float*)d_in[7];
    const float* Wk      = (const float*)d_in[8];
    const float* bk      = (const float*)d_in[9];
    const float* Wv      = (const float*)d_in[10];
    const float* bv      = (const float*)d_in[11];
    const float* Wo      = (const float*)d_in[12];
    const float* bo      = (const float*)d_in[13];
    const float* hb      = (const float*)d_in[14];
    const float* beta    = (const float*)d_in[15];
    const float* tau_raw = (const float*)d_in[16];
    const float* gammaP  = (const float*)d_in[17];
    const float* deltaP  = (const float*)d_in[18];
    float* out = (float*)d_out;

    float *proj, *agg;
    cudaGetSymbolAddress((void**)&proj, g_proj);
    cudaGetSymbolAddress((void**)&agg, g_agg);

    cudaFuncSetAttribute(gemm128_kernel,
                         cudaFuncAttributeMaxDynamicSharedMemorySize, GEMM_SMEM);

    clear_kernel<<<512, 256>>>();
    build_ht_kernel<<<(2 * E + 255) / 256, 256>>>(eui, eiu);

    int gblocks = (NN + 127) / 128;   // 313
    gemm128_kernel<<<gblocks, 256, GEMM_SMEM>>>(x_user, NN, Wq, bq, proj + (size_t)0 * NN * C);
    gemm128_kernel<<<gblocks, 256, GEMM_SMEM>>>(x_user, NN, Wk, bk, proj + (size_t)1 * NN * C);
    gemm128_kernel<<<gblocks, 256, GEMM_SMEM>>>(x_user, NN, Wv, bv, proj + (size_t)2 * NN * C);
    gemm128_kernel<<<gblocks, 256, GEMM_SMEM>>>(x_item, NN, Wq, bq, proj + (size_t)3 * NN * C);
    gemm128_kernel<<<gblocks, 256, GEMM_SMEM>>>(x_item, NN, Wk, bk, proj + (size_t)4 * NN * C);
    gemm128_kernel<<<gblocks, 256, GEMM_SMEM>>>(x_item, NN, Wv, bv, proj + (size_t)5 * NN * C);

    dim3 sgrid((E * 32 + 255) / 256, 2);
    score_kernel<<<sgrid, 256>>>(eui, eiu, t_user, t_item, hb, beta, tau_raw, gammaP, deltaP);
    dim3 egrid((E * H + 255) / 256, 2);
    expsum_kernel<<<egrid, 256>>>(eui, eiu);
    aggregate_kernel<<<sgrid, 256>>>(eui, eiu);

    // relation 0 (user->item) feeds out_item; relation 1 feeds out_user
    gemm128_kernel<<<gblocks, 256, GEMM_SMEM>>>(agg + (size_t)0 * NN * C, NN, Wo, nullptr, out + (size_t)NN * C);
    gemm128_kernel<<<gblocks, 256, GEMM_SMEM>>>(agg + (size_t)1 * NN * C, NN, Wo, nullptr, out);

    dim3 fgrid((NN * 32 + 255) / 256, 2);
    final_kernel<<<fgrid, 256>>>(x_user, x_item, bo, out);
}

// round 4
// speedup vs baseline: 1.6612x; 1.6612x over previous
#include <cuda_runtime.h>
#include <cuda_bf16.h>
#include <cstdint>
#include <math.h>

#define NU 40000
#define NI 40000
#define NN 40000
#define C 128
#define H 4
#define HD 32
#define E 200000
#define HSIZE (1 << 19)
#define HMASK (HSIZE - 1)

// ---------------- device scratch (static, no allocs) ----------------
__device__ int   g_ht_keys[4 * HSIZE];
__device__ int   g_ht_cnt [4 * HSIZE];
__device__ float g_proj[6 * NN * C];     // 0:Qu 1:Ku 2:Vu 3:Qi 4:Ki 5:Vi
__device__ float g_agg [2 * NN * C];     // weighted-V aggregate per relation
__device__ float g_score[2 * E * H];     // raw scores, then exp values
__device__ unsigned g_mx[2 * NN * H];    // encoded running max
__device__ float g_z [2 * NN * H];       // softmax denominators
__device__ int g_cnt_su[NN], g_cnt_du[NN], g_cnt_si[NN], g_cnt_di[NN];

// ---------------- helpers ----------------
__device__ __forceinline__ unsigned hash_key(int key) {
    unsigned h = (unsigned)key * 2654435761u;
    h ^= h >> 15;
    return h & HMASK;
}

__device__ __forceinline__ void ht_insert(int t, int key) {
    unsigned slot = hash_key(key);
    int* keys = g_ht_keys + t * HSIZE;
    int* cnts = g_ht_cnt + t * HSIZE;
    while (true) {
        int k = keys[slot];
        if (k == key) { atomicAdd(&cnts[slot], 1); return; }
        if (k == -1) {
            int old = atomicCAS(&keys[slot], -1, key);
            if (old == -1 || old == key) { atomicAdd(&cnts[slot], 1); return; }
        }
        slot = (slot + 1) & HMASK;
    }
}

__device__ __forceinline__ int ht_query(int t, int key) {
    unsigned slot = hash_key(key);
    const int* keys = g_ht_keys + t * HSIZE;
    const int* cnts = g_ht_cnt + t * HSIZE;
    while (true) {
        int k = keys[slot];
        if (k == key) return cnts[slot];
        if (k == -1) return 0;
        slot = (slot + 1) & HMASK;
    }
}

// order-preserving float -> uint encoding for atomicMax
__device__ __forceinline__ unsigned fenc(float f) {
    unsigned u = __float_as_uint(f);
    return (u & 0x80000000u) ? ~u : (u | 0x80000000u);
}
__device__ __forceinline__ float fdec(unsigned u) {
    unsigned v = (u & 0x80000000u) ? (u & 0x7FFFFFFFu) : ~u;
    return __uint_as_float(v);
}

__device__ __forceinline__ float cvt_tf32(float x) {
    uint32_t u;
    asm("cvt.rna.tf32.f32 %0, %1;" : "=r"(u) : "f"(x));
    return __uint_as_float(u);
}

__device__ __forceinline__ void mma_tf32(float* c, const uint32_t* a, const uint32_t* b) {
    asm volatile(
        "mma.sync.aligned.m16n8k8.row.col.f32.tf32.tf32.f32 "
        "{%0,%1,%2,%3}, {%4,%5,%6,%7}, {%8,%9}, {%0,%1,%2,%3};"
        : "+f"(c[0]), "+f"(c[1]), "+f"(c[2]), "+f"(c[3])
        : "r"(a[0]), "r"(a[1]), "r"(a[2]), "r"(a[3]), "r"(b[0]), "r"(b[1]));
}

// ---------------- kernels ----------------
__global__ void clear_kernel() {
    int gid = blockIdx.x * blockDim.x + threadIdx.x;
    int T = gridDim.x * blockDim.x;
    for (int i = gid; i < 4 * HSIZE; i += T) { g_ht_keys[i] = -1; g_ht_cnt[i] = 0; }
    for (int i = gid; i < 2 * NN * H; i += T) { g_mx[i] = 0u; g_z[i] = 0.f; }
    for (int i = gid; i < 2 * NN * C; i += T) g_agg[i] = 0.f;
    for (int i = gid; i < NN; i += T) {
        g_cnt_su[i] = 0; g_cnt_du[i] = 0; g_cnt_si[i] = 0; g_cnt_di[i] = 0;
    }
}

__global__ void build_ht_kernel(const int* __restrict__ eui, const int* __restrict__ eiu) {
    int e = blockIdx.x * blockDim.x + threadIdx.x;
    if (e >= 2 * E) return;
    if (e < E) {
        int su = eui[e], du = eui[e + E];
        ht_insert(0, su * NI + du);      // pid_ui multiset
        ht_insert(3, du * NU + su);      // rev pairs for iu relation
        atomicAdd(&g_cnt_su[su], 1);
        atomicAdd(&g_cnt_du[du], 1);
    } else {
        int i = e - E;
        int si = eiu[i], di = eiu[i + E];
        ht_insert(1, si * NU + di);      // pid_iu multiset
        ht_insert(2, di * NI + si);      // rev pairs for ui relation
        atomicAdd(&g_cnt_si[si], 1);
        atomicAdd(&g_cnt_di[di], 1);
    }
}

// ------------- tf32 tensor-core GEMM: C[m][n] = sum_k A[m][k]*W[n][k] (+b[n]) -------------
struct GemmJob { const float* A; const float* W; const float* bias; float* out; };
struct GemmJobs6 { GemmJob j[6]; };

#define GSM_STRIDE 132
#define GSM_BYTES (2 * 128 * GSM_STRIDE * 4)

__global__ __launch_bounds__(256) void gemm_tf32_kernel(GemmJobs6 jobs, int M) {
    const GemmJob jb = jobs.j[blockIdx.y];
    extern __shared__ float sh[];
    float* As = sh;                     // [128][132] tf32
    float* Ws = sh + 128 * GSM_STRIDE;  // [128][132] tf32 (row n, col k)
    int tid = threadIdx.x;
    int row0 = blockIdx.x * 128;

    // global -> shared, converting to tf32 once
    for (int i = tid; i < 128 * 32; i += 256) {
        int r = i >> 5, c4 = (i & 31) << 2;
        float4 v = make_float4(0.f, 0.f, 0.f, 0.f);
        if (row0 + r < M) v = *(const float4*)(jb.A + (size_t)(row0 + r) * 128 + c4);
        v.x = cvt_tf32(v.x); v.y = cvt_tf32(v.y);
        v.z = cvt_tf32(v.z); v.w = cvt_tf32(v.w);
        *(float4*)(As + r * GSM_STRIDE + c4) = v;
        float4 w = *(const float4*)(jb.W + r * 128 + c4);
        w.x = cvt_tf32(w.x); w.y = cvt_tf32(w.y);
        w.z = cvt_tf32(w.z); w.w = cvt_tf32(w.w);
        *(float4*)(Ws + r * GSM_STRIDE + c4) = w;
    }
    __syncthreads();

    int warp = tid >> 5, lane = tid & 31;
    int wm = warp >> 1, wn = warp & 1;      // 4 (M) x 2 (N) warps
    int g = lane >> 2, t4 = lane & 3;

    float acc[2][8][4];
    #pragma unroll
    for (int mt = 0; mt < 2; mt++)
        #pragma unroll
        for (int nt = 0; nt < 8; nt++)
            #pragma unroll
            for (int q = 0; q < 4; q++) acc[mt][nt][q] = 0.f;

    const float* Abase = As + (wm * 32 + g) * GSM_STRIDE + t4;
    const float* Bbase = Ws + (wn * 64 + g) * GSM_STRIDE + t4;

    #pragma unroll
    for (int ks = 0; ks < 16; ks++) {
        int k0 = ks * 8;
        uint32_t a[2][4], b[8][2];
        #pragma unroll
        for (int mt = 0; mt < 2; mt++) {
            const float* ap = Abase + mt * 16 * GSM_STRIDE + k0;
            a[mt][0] = __float_as_uint(ap[0]);
            a[mt][1] = __float_as_uint(ap[8 * GSM_STRIDE]);
            a[mt][2] = __float_as_uint(ap[4]);
            a[mt][3] = __float_as_uint(ap[8 * GSM_STRIDE + 4]);
        }
        #pragma unroll
        for (int nt = 0; nt < 8; nt++) {
            const float* bp = Bbase + nt * 8 * GSM_STRIDE + k0;
            b[nt][0] = __float_as_uint(bp[0]);
            b[nt][1] = __float_as_uint(bp[4]);
        }
        #pragma unroll
        for (int mt = 0; mt < 2; mt++)
            #pragma unroll
            for (int nt = 0; nt < 8; nt++)
                mma_tf32(acc[mt][nt], a[mt], b[nt]);
    }

    // epilogue: c0,c1 -> row g, cols 2*t4, 2*t4+1 ; c2,c3 -> row g+8
    #pragma unroll
    for (int mt = 0; mt < 2; mt++) {
        #pragma unroll
        for (int half = 0; half < 2; half++) {
            int row = row0 + wm * 32 + mt * 16 + g + half * 8;
            if (row >= M) continue;
            float* orow = jb.out + (size_t)row * 128 + wn * 64;
            #pragma unroll
            for (int nt = 0; nt < 8; nt++) {
                int col = nt * 8 + t4 * 2;
                float b0 = 0.f, b1 = 0.f;
                if (jb.bias) {
                    b0 = jb.bias[wn * 64 + col];
                    b1 = jb.bias[wn * 64 + col + 1];
                }
                float2 o = make_float2(acc[mt][nt][half * 2 + 0] + b0,
                                       acc[mt][nt][half * 2 + 1] + b1);
                *(float2*)(orow + col) = o;
            }
        }
    }
}

// pass A: scores + per-(dst,head) running max. one warp per edge.
__global__ void score_kernel(const int* __restrict__ eui, const int* __restrict__ eiu,
                             const float* __restrict__ t_user, const float* __restrict__ t_item,
                             const float* __restrict__ hb, const float* __restrict__ beta,
                             const float* __restrict__ tau_raw,
                             const float* __restrict__ gamma, const float* __restrict__ delta) {
    int wg = (blockIdx.x * blockDim.x + threadIdx.x) >> 5;
    int lane = threadIdx.x & 31;
    int r = blockIdx.y;
    if (wg >= E) return;
    int e = wg;
    const int* ei = r ? eiu : eui;
    int src = ei[e], dst = ei[e + E];
    const float* Q = g_proj + (size_t)(r == 0 ? 3 : 0) * NN * C + (size_t)dst * C;
    const float* K = g_proj + (size_t)(r == 0 ? 1 : 4) * NN * C + (size_t)src * C;
    float4 q = *(const float4*)(Q + lane * 4);
    float4 k = *(const float4*)(K + lane * 4);
    float p = q.x * k.x + q.y * k.y + q.z * k.z + q.w * k.w;
    p += __shfl_xor_sync(0xffffffffu, p, 1);
    p += __shfl_xor_sync(0xffffffffu, p, 2);
    p += __shfl_xor_sync(0xffffffffu, p, 4);

    float dtc = 0.f, cntf = 0.f, recf = 0.f;
    if (lane == 0) {
        float ts = (r == 0 ? t_user : t_item)[src];
        float td = (r == 0 ? t_item : t_user)[dst];
        dtc = fabsf(td - ts) + 1e-6f;
        int pid = src * 40000 + dst;
        cntf = (float)(ht_query(r, pid) - 1);
        recf = (ht_query(2 + r, pid) > 0) ? 1.f : 0.f;
    }
    dtc  = __shfl_sync(0xffffffffu, dtc, 0);
    cntf = __shfl_sync(0xffffffffu, cntf, 0);
    recf = __shfl_sync(0xffffffffu, recf, 0);

    if ((lane & 7) == 0) {
        int h = lane >> 3;
        float tr = tau_raw[r];
        float tau = log1pf(expf(tr)) + 1e-6f;
        float s = p * 0.1767766952966369f + hb[r * H + h]
                - log1pf(dtc / tau) * beta[r * H + h]
                + log1pf(cntf) * gamma[r * H + h]
                + recf * delta[r * H + h];
        g_score[(size_t)r * E * H + (size_t)e * H + h] = s;
        atomicMax(&g_mx[r * NN * H + dst * H + h], fenc(s));
    }
}

// pass B: exp(s - max), accumulate denominators. one thread per (edge, head).
__global__ void expsum_kernel(const int* __restrict__ eui, const int* __restrict__ eiu) {
    int idx = blockIdx.x * blockDim.x + threadIdx.x;
    if (idx >= E * H) return;
    int r = blockIdx.y;
    int e = idx >> 2, h = idx & 3;
    const int* ei = r ? eiu : eui;
    int dst = ei[e + E];
    float m = fdec(g_mx[r * NN * H + dst * H + h]);
    float ex = expf(g_score[(size_t)r * E * H + idx] - m);
    g_score[(size_t)r * E * H + idx] = ex;
    atomicAdd(&g_z[r * NN * H + dst * H + h], ex);
}

// pass C: w = exp/z, scatter-add w*V into per-dst aggregate. one warp per edge.
__global__ void aggregate_kernel(const int* __restrict__ eui, const int* __restrict__ eiu) {
    int wg = (blockIdx.x * blockDim.x + threadIdx.x) >> 5;
    int lane = threadIdx.x & 31;
    int r = blockIdx.y;
    if (wg >= E) return;
    int e = wg;
    const int* ei = r ? eiu : eui;
    int src = ei[e], dst = ei[e + E];
    int h = lane >> 3;
    float w = g_score[(size_t)r * E * H + (size_t)e * H + h]
            / g_z[r * NN * H + dst * H + h];
    const float* V = g_proj + (size_t)(r == 0 ? 2 : 5) * NN * C + (size_t)src * C;
    float4 v = *(const float4*)(V + lane * 4);
    float* ag = g_agg + (size_t)r * NN * C + (size_t)dst * C + lane * 4;
    atomicAdd(ag + 0, v.x * w);
    atomicAdd(ag + 1, v.y * w);
    atomicAdd(ag + 2, v.z * w);
    atomicAdd(ag + 3, v.w * w);
}

// final: out = LayerNorm(proj + indeg*bo + deg + x). one warp per node.
__global__ void final_kernel(const float* __restrict__ x_user, const float* __restrict__ x_item,
                             const float* __restrict__ bo, float* __restrict__ out) {
    int n = (blockIdx.x * blockDim.x + threadIdx.x) >> 5;
    int lane = threadIdx.x & 31;
    int ty = blockIdx.y;     // 0 = user, 1 = item
    if (n >= NN) return;
    float* o = out + (ty == 0 ? (size_t)0 : (size_t)NN * C) + (size_t)n * C;
    const float* x = (ty == 0 ? x_user : x_item) + (size_t)n * C;
    float indeg = (float)(ty == 0 ? g_cnt_di[n] : g_cnt_du[n]);
    float deg = (float)(ty == 0 ? (g_cnt_su[n] + g_cnt_di[n])
                                : (g_cnt_du[n] + g_cnt_si[n]));
    float4 v  = *(float4*)(o + lane * 4);
    float4 xv = *(const float4*)(x + lane * 4);
    float4 bv = *(const float4*)(bo + lane * 4);
    v.x += xv.x + indeg * bv.x + deg;
    v.y += xv.y + indeg * bv.y + deg;
    v.z += xv.z + indeg * bv.z + deg;
    v.w += xv.w + indeg * bv.w + deg;
    float s = v.x + v.y + v.z + v.w;
    #pragma unroll
    for (int d = 16; d; d >>= 1) s += __shfl_xor_sync(0xffffffffu, s, d);
    float mu = s * (1.f / 128.f);
    float d0 = v.x - mu, d1 = v.y - mu, d2 = v.z - mu, d3 = v.w - mu;
    float q = d0 * d0 + d1 * d1 + d2 * d2 + d3 * d3;
    #pragma unroll
    for (int d = 16; d; d >>= 1) q += __shfl_xor_sync(0xffffffffu, q, d);
    float inv = 1.f / sqrtf(q * (1.f / 128.f) + 1e-5f);
    float4 r4 = make_float4(d0 * inv, d1 * inv, d2 * inv, d3 * inv);
    *(float4*)(o + lane * 4) = r4;
}

// ---------------- launch ----------------
extern "C" void kernel_launch(void* const* d_in, const int* in_sizes, int n_in,
                              void* d_out, int out_size) {
    const float* x_user  = (const float*)d_in[0];
    const float* x_item  = (const float*)d_in[1];
    const float* t_user  = (const float*)d_in[2];
    const float* t_item  = (const float*)d_in[3];
    const int*   eui     = (const int*)d_in[4];
    const int*   eiu     = (const int*)d_in[5];
    const float* Wq      = (const float*)d_in[6];
    const float* bq      = (const float*)d_in[7];
    const float* Wk      = (const float*)d_in[8];
    const float* bk      = (const float*)d_in[9];
    const float* Wv      = (const float*)d_in[10];
    const float* bv      = (const float*)d_in[11];
    const float* Wo      = (const float*)d_in[12];
    const float* bo      = (const float*)d_in[13];
    const float* hb      = (const float*)d_in[14];
    const float* beta    = (const float*)d_in[15];
    const float* tau_raw = (const float*)d_in[16];
    const float* gammaP  = (const float*)d_in[17];
    const float* deltaP  = (const float*)d_in[18];
    float* out = (float*)d_out;

    float *proj, *agg;
    cudaGetSymbolAddress((void**)&proj, g_proj);
    cudaGetSymbolAddress((void**)&agg, g_agg);

    cudaFuncSetAttribute(gemm_tf32_kernel,
                         cudaFuncAttributeMaxDynamicSharedMemorySize, GSM_BYTES);

    clear_kernel<<<512, 256>>>();
    build_ht_kernel<<<(2 * E + 255) / 256, 256>>>(eui, eiu);

    int gblocks = (NN + 127) / 128;   // 313

    GemmJobs6 qkv;
    qkv.j[0] = { x_user, Wq, bq, proj + (size_t)0 * NN * C };
    qkv.j[1] = { x_user, Wk, bk, proj + (size_t)1 * NN * C };
    qkv.j[2] = { x_user, Wv, bv, proj + (size_t)2 * NN * C };
    qkv.j[3] = { x_item, Wq, bq, proj + (size_t)3 * NN * C };
    qkv.j[4] = { x_item, Wk, bk, proj + (size_t)4 * NN * C };
    qkv.j[5] = { x_item, Wv, bv, proj + (size_t)5 * NN * C };
    gemm_tf32_kernel<<<dim3(gblocks, 6), 256, GSM_BYTES>>>(qkv, NN);

    dim3 sgrid((E * 32 + 255) / 256, 2);
    score_kernel<<<sgrid, 256>>>(eui, eiu, t_user, t_item, hb, beta, tau_raw, gammaP, deltaP);
    dim3 egrid((E * H + 255) / 256, 2);
    expsum_kernel<<<egrid, 256>>>(eui, eiu);
    aggregate_kernel<<<sgrid, 256>>>(eui, eiu);

    // relation 0 (user->item) feeds out_item; relation 1 feeds out_user
    GemmJobs6 ojobs;
    ojobs.j[0] = { agg + (size_t)0 * NN * C, Wo, nullptr, out + (size_t)NN * C };
    ojobs.j[1] = { agg + (size_t)1 * NN * C, Wo, nullptr, out };
    ojobs.j[2] = ojobs.j[0]; ojobs.j[3] = ojobs.j[0];
    ojobs.j[4] = ojobs.j[0]; ojobs.j[5] = ojobs.j[0];
    gemm_tf32_kernel<<<dim3(gblocks, 2), 256, GSM_BYTES>>>(ojobs, NN);

    dim3 fgrid((NN * 32 + 255) / 256, 2);
    final_kernel<<<fgrid, 256>>>(x_user, x_item, bo, out);
}

// round 5
// speedup vs baseline: 2.3675x; 1.4251x over previous
#include <cuda_runtime.h>
#include <cuda_bf16.h>
#include <cstdint>
#include <math.h>

#define NU 40000
#define NI 40000
#define NN 40000
#define C 128
#define H 4
#define HD 32
#define E 200000
#define HSIZE (1 << 19)
#define HMASK (HSIZE - 1)

// ---------------- device scratch (static, no allocs) ----------------
__device__ int   g_ht_keys[4 * HSIZE];
__device__ int   g_ht_cnt [4 * HSIZE];
__device__ float g_proj[6 * NN * C];     // 0:Qu 1:Ku 2:Vu 3:Qi 4:Ki 5:Vi
__device__ float g_agg [2 * NN * C];     // weighted-V aggregate per relation
__device__ int g_cnt_su[NN], g_cnt_du[NN], g_cnt_si[NN], g_cnt_di[NN];
__device__ int g_off0[NN], g_off1[NN];   // CSR offsets (rel0 dst=item, rel1 dst=user)
__device__ int g_cur0[NN], g_cur1[NN];   // scatter cursors
__device__ int    g_src_s[2 * E];        // CSR-sorted source ids
__device__ float4 g_bias4[2 * E];        // per-edge per-head score bias (precomputed)

// ---------------- helpers ----------------
__device__ __forceinline__ unsigned hash_key(int key) {
    unsigned h = (unsigned)key * 2654435761u;
    h ^= h >> 15;
    return h & HMASK;
}

__device__ __forceinline__ void ht_insert(int t, int key) {
    unsigned slot = hash_key(key);
    int* keys = g_ht_keys + t * HSIZE;
    int* cnts = g_ht_cnt + t * HSIZE;
    while (true) {
        int k = keys[slot];
        if (k == key) { atomicAdd(&cnts[slot], 1); return; }
        if (k == -1) {
            int old = atomicCAS(&keys[slot], -1, key);
            if (old == -1 || old == key) { atomicAdd(&cnts[slot], 1); return; }
        }
        slot = (slot + 1) & HMASK;
    }
}

__device__ __forceinline__ int ht_query(int t, int key) {
    unsigned slot = hash_key(key);
    const int* keys = g_ht_keys + t * HSIZE;
    const int* cnts = g_ht_cnt + t * HSIZE;
    while (true) {
        int k = keys[slot];
        if (k == key) return cnts[slot];
        if (k == -1) return 0;
        slot = (slot + 1) & HMASK;
    }
}

__device__ __forceinline__ float cvt_tf32(float x) {
    uint32_t u;
    asm("cvt.rna.tf32.f32 %0, %1;" : "=r"(u) : "f"(x));
    return __uint_as_float(u);
}

__device__ __forceinline__ void mma_tf32(float* c, const uint32_t* a, const uint32_t* b) {
    asm volatile(
        "mma.sync.aligned.m16n8k8.row.col.f32.tf32.tf32.f32 "
        "{%0,%1,%2,%3}, {%4,%5,%6,%7}, {%8,%9}, {%0,%1,%2,%3};"
        : "+f"(c[0]), "+f"(c[1]), "+f"(c[2]), "+f"(c[3])
        : "r"(a[0]), "r"(a[1]), "r"(a[2]), "r"(a[3]), "r"(b[0]), "r"(b[1]));
}

// ---------------- kernels ----------------
__global__ void clear_kernel() {
    int gid = blockIdx.x * blockDim.x + threadIdx.x;
    int T = gridDim.x * blockDim.x;
    for (int i = gid; i < 4 * HSIZE; i += T) { g_ht_keys[i] = -1; g_ht_cnt[i] = 0; }
    for (int i = gid; i < NN; i += T) {
        g_cnt_su[i] = 0; g_cnt_du[i] = 0; g_cnt_si[i] = 0; g_cnt_di[i] = 0;
        g_cur0[i] = 0; g_cur1[i] = 0;
    }
}

__global__ void build_ht_kernel(const int* __restrict__ eui, const int* __restrict__ eiu) {
    int e = blockIdx.x * blockDim.x + threadIdx.x;
    if (e >= 2 * E) return;
    if (e < E) {
        int su = eui[e], du = eui[e + E];
        ht_insert(0, su * NI + du);      // pid_ui multiset
        ht_insert(3, du * NU + su);      // rev pairs for iu relation
        atomicAdd(&g_cnt_su[su], 1);
        atomicAdd(&g_cnt_du[du], 1);
    } else {
        int i = e - E;
        int si = eiu[i], di = eiu[i + E];
        ht_insert(1, si * NU + di);      // pid_iu multiset
        ht_insert(2, di * NI + si);      // rev pairs for ui relation
        atomicAdd(&g_cnt_si[si], 1);
        atomicAdd(&g_cnt_di[di], 1);
    }
}

// exclusive prefix scan of per-dst degree -> CSR offsets. one block per relation.
__global__ __launch_bounds__(1024) void scan_kernel() {
    int which = blockIdx.x;
    const int* cnt = which ? g_cnt_di : g_cnt_du;
    int* off = which ? g_off1 : g_off0;
    __shared__ int wsum[32];
    __shared__ int carry;
    int tid = threadIdx.x, lane = tid & 31, wid = tid >> 5;
    if (tid == 0) carry = 0;
    __syncthreads();
    for (int base = 0; base < NN; base += 1024) {
        int i = base + tid;
        int v = (i < NN) ? cnt[i] : 0;
        int x = v;
        #pragma unroll
        for (int d = 1; d < 32; d <<= 1) {
            int y = __shfl_up_sync(0xffffffffu, x, d);
            if (lane >= d) x += y;
        }
        if (lane == 31) wsum[wid] = x;
        __syncthreads();
        if (wid == 0) {
            int s = wsum[lane];
            #pragma unroll
            for (int d = 1; d < 32; d <<= 1) {
                int y = __shfl_up_sync(0xffffffffu, s, d);
                if (lane >= d) s += y;
            }
            wsum[lane] = s;   // inclusive across warps
        }
        __syncthreads();
        int wprefix = (wid == 0) ? 0 : wsum[wid - 1];
        int excl = carry + wprefix + (x - v);
        if (i < NN) off[i] = excl;
        __syncthreads();
        if (tid == 0) carry += wsum[31];
        __syncthreads();
    }
}

// scatter edges into CSR order + precompute per-edge head bias float4
__global__ void scatter_kernel(const int* __restrict__ eui, const int* __restrict__ eiu,
                               const float* __restrict__ t_user, const float* __restrict__ t_item,
                               const float* __restrict__ hb, const float* __restrict__ beta,
                               const float* __restrict__ tau_raw,
                               const float* __restrict__ gamma, const float* __restrict__ delta) {
    int idx = blockIdx.x * blockDim.x + threadIdx.x;
    if (idx >= 2 * E) return;
    int r = (idx >= E) ? 1 : 0;
    int e = idx - r * E;
    const int* ei = r ? eiu : eui;
    int src = ei[e], dst = ei[e + E];
    int* cur = r ? g_cur1 : g_cur0;
    const int* off = r ? g_off1 : g_off0;
    int pos = off[dst] + atomicAdd(&cur[dst], 1);
    g_src_s[r * E + pos] = src;

    float ts = (r ? t_item : t_user)[src];
    float td = (r ? t_user : t_item)[dst];
    float dt = fabsf(td - ts) + 1e-6f;
    int pid = src * 40000 + dst;
    float cntf = (float)(ht_query(r, pid) - 1);
    float recf = (ht_query(2 + r, pid) > 0) ? 1.f : 0.f;
    float tau = log1pf(expf(tau_raw[r])) + 1e-6f;
    float a = -log1pf(dt / tau);
    float b = log1pf(cntf);
    float4 bias;
    bias.x = hb[r * H + 0] + a * beta[r * H + 0] + b * gamma[r * H + 0] + recf * delta[r * H + 0];
    bias.y = hb[r * H + 1] + a * beta[r * H + 1] + b * gamma[r * H + 1] + recf * delta[r * H + 1];
    bias.z = hb[r * H + 2] + a * beta[r * H + 2] + b * gamma[r * H + 2] + recf * delta[r * H + 2];
    bias.w = hb[r * H + 3] + a * beta[r * H + 3] + b * gamma[r * H + 3] + recf * delta[r * H + 3];
    g_bias4[r * E + pos] = bias;
}

// fused edge attention: warp per destination, online softmax + weighted-V accumulate.
__global__ __launch_bounds__(256) void attn_kernel() {
    int n = (blockIdx.x * blockDim.x + threadIdx.x) >> 5;
    int lane = threadIdx.x & 31;
    int r = blockIdx.y;
    if (n >= NN) return;

    const float* Q     = g_proj + (size_t)(r == 0 ? 3 : 0) * NN * C + (size_t)n * C;
    const float* Kbase = g_proj + (size_t)(r == 0 ? 1 : 4) * NN * C;
    const float* Vbase = g_proj + (size_t)(r == 0 ? 2 : 5) * NN * C;
    const int* off = r ? g_off1 : g_off0;
    int s0 = off[n];
    int s1 = (n + 1 < NN) ? off[n + 1] : E;

    float4 q = *(const float4*)(Q + lane * 4);
    int h = lane >> 3;

    float m = -INFINITY, z = 0.f;
    float a0 = 0.f, a1 = 0.f, a2 = 0.f, a3 = 0.f;

    for (int j = s0; j < s1; j++) {
        int src = g_src_s[r * E + j];
        const float4 k = *(const float4*)(Kbase + (size_t)src * C + lane * 4);
        float p = q.x * k.x + q.y * k.y + q.z * k.z + q.w * k.w;
        p += __shfl_xor_sync(0xffffffffu, p, 1);
        p += __shfl_xor_sync(0xffffffffu, p, 2);
        p += __shfl_xor_sync(0xffffffffu, p, 4);   // 8-lane group = this head's dot

        float4 bias = g_bias4[r * E + j];
        float bh = (h == 0) ? bias.x : (h == 1) ? bias.y : (h == 2) ? bias.z : bias.w;
        float s = p * 0.1767766952966369f + bh;

        float mn = fmaxf(m, s);
        float fac = __expf(m - mn);     // first iter: exp(-inf) = 0
        float es  = __expf(s - mn);
        z = z * fac + es;
        const float4 v = *(const float4*)(Vbase + (size_t)src * C + lane * 4);
        a0 = a0 * fac + es * v.x;
        a1 = a1 * fac + es * v.y;
        a2 = a2 * fac + es * v.z;
        a3 = a3 * fac + es * v.w;
        m = mn;
    }

    float inv = (z > 0.f) ? 1.f / z : 0.f;
    float* ag = g_agg + (size_t)r * NN * C + (size_t)n * C + lane * 4;
    *(float4*)ag = make_float4(a0 * inv, a1 * inv, a2 * inv, a3 * inv);
}

// ------------- tf32 tensor-core GEMM: C[m][n] = sum_k A[m][k]*W[n][k] (+b[n]) -------------
struct GemmJob { const float* A; const float* W; const float* bias; float* out; };
struct GemmJobs6 { GemmJob j[6]; };

#define GSM_STRIDE 132
#define GSM_BYTES (2 * 128 * GSM_STRIDE * 4)

__global__ __launch_bounds__(256) void gemm_tf32_kernel(GemmJobs6 jobs, int M) {
    const GemmJob jb = jobs.j[blockIdx.y];
    extern __shared__ float sh[];
    float* As = sh;                     // [128][132] tf32
    float* Ws = sh + 128 * GSM_STRIDE;  // [128][132] tf32 (row n, col k)
    int tid = threadIdx.x;
    int row0 = blockIdx.x * 128;

    for (int i = tid; i < 128 * 32; i += 256) {
        int r = i >> 5, c4 = (i & 31) << 2;
        float4 v = make_float4(0.f, 0.f, 0.f, 0.f);
        if (row0 + r < M) v = *(const float4*)(jb.A + (size_t)(row0 + r) * 128 + c4);
        v.x = cvt_tf32(v.x); v.y = cvt_tf32(v.y);
        v.z = cvt_tf32(v.z); v.w = cvt_tf32(v.w);
        *(float4*)(As + r * GSM_STRIDE + c4) = v;
        float4 w = *(const float4*)(jb.W + r * 128 + c4);
        w.x = cvt_tf32(w.x); w.y = cvt_tf32(w.y);
        w.z = cvt_tf32(w.z); w.w = cvt_tf32(w.w);
        *(float4*)(Ws + r * GSM_STRIDE + c4) = w;
    }
    __syncthreads();

    int warp = tid >> 5, lane = tid & 31;
    int wm = warp >> 1, wn = warp & 1;
    int g = lane >> 2, t4 = lane & 3;

    float acc[2][8][4];
    #pragma unroll
    for (int mt = 0; mt < 2; mt++)
        #pragma unroll
        for (int nt = 0; nt < 8; nt++)
            #pragma unroll
            for (int q = 0; q < 4; q++) acc[mt][nt][q] = 0.f;

    const float* Abase = As + (wm * 32 + g) * GSM_STRIDE + t4;
    const float* Bbase = Ws + (wn * 64 + g) * GSM_STRIDE + t4;

    #pragma unroll
    for (int ks = 0; ks < 16; ks++) {
        int k0 = ks * 8;
        uint32_t a[2][4], b[8][2];
        #pragma unroll
        for (int mt = 0; mt < 2; mt++) {
            const float* ap = Abase + mt * 16 * GSM_STRIDE + k0;
            a[mt][0] = __float_as_uint(ap[0]);
            a[mt][1] = __float_as_uint(ap[8 * GSM_STRIDE]);
            a[mt][2] = __float_as_uint(ap[4]);
            a[mt][3] = __float_as_uint(ap[8 * GSM_STRIDE + 4]);
        }
        #pragma unroll
        for (int nt = 0; nt < 8; nt++) {
            const float* bp = Bbase + nt * 8 * GSM_STRIDE + k0;
            b[nt][0] = __float_as_uint(bp[0]);
            b[nt][1] = __float_as_uint(bp[4]);
        }
        #pragma unroll
        for (int mt = 0; mt < 2; mt++)
            #pragma unroll
            for (int nt = 0; nt < 8; nt++)
                mma_tf32(acc[mt][nt], a[mt], b[nt]);
    }

    #pragma unroll
    for (int mt = 0; mt < 2; mt++) {
        #pragma unroll
        for (int half = 0; half < 2; half++) {
            int row = row0 + wm * 32 + mt * 16 + g + half * 8;
            if (row >= M) continue;
            float* orow = jb.out + (size_t)row * 128 + wn * 64;
            #pragma unroll
            for (int nt = 0; nt < 8; nt++) {
                int col = nt * 8 + t4 * 2;
                float b0 = 0.f, b1 = 0.f;
                if (jb.bias) {
                    b0 = jb.bias[wn * 64 + col];
                    b1 = jb.bias[wn * 64 + col + 1];
                }
                float2 o = make_float2(acc[mt][nt][half * 2 + 0] + b0,
                                       acc[mt][nt][half * 2 + 1] + b1);
                *(float2*)(orow + col) = o;
            }
        }
    }
}

// final: out = LayerNorm(proj + indeg*bo + deg + x). one warp per node.
__global__ void final_kernel(const float* __restrict__ x_user, const float* __restrict__ x_item,
                             const float* __restrict__ bo, float* __restrict__ out) {
    int n = (blockIdx.x * blockDim.x + threadIdx.x) >> 5;
    int lane = threadIdx.x & 31;
    int ty = blockIdx.y;     // 0 = user, 1 = item
    if (n >= NN) return;
    float* o = out + (ty == 0 ? (size_t)0 : (size_t)NN * C) + (size_t)n * C;
    const float* x = (ty == 0 ? x_user : x_item) + (size_t)n * C;
    float indeg = (float)(ty == 0 ? g_cnt_di[n] : g_cnt_du[n]);
    float deg = (float)(ty == 0 ? (g_cnt_su[n] + g_cnt_di[n])
                                : (g_cnt_du[n] + g_cnt_si[n]));
    float4 v  = *(float4*)(o + lane * 4);
    float4 xv = *(const float4*)(x + lane * 4);
    float4 bv = *(const float4*)(bo + lane * 4);
    v.x += xv.x + indeg * bv.x + deg;
    v.y += xv.y + indeg * bv.y + deg;
    v.z += xv.z + indeg * bv.z + deg;
    v.w += xv.w + indeg * bv.w + deg;
    float s = v.x + v.y + v.z + v.w;
    #pragma unroll
    for (int d = 16; d; d >>= 1) s += __shfl_xor_sync(0xffffffffu, s, d);
    float mu = s * (1.f / 128.f);
    float d0 = v.x - mu, d1 = v.y - mu, d2 = v.z - mu, d3 = v.w - mu;
    float q = d0 * d0 + d1 * d1 + d2 * d2 + d3 * d3;
    #pragma unroll
    for (int d = 16; d; d >>= 1) q += __shfl_xor_sync(0xffffffffu, q, d);
    float inv = 1.f / sqrtf(q * (1.f / 128.f) + 1e-5f);
    float4 r4 = make_float4(d0 * inv, d1 * inv, d2 * inv, d3 * inv);
    *(float4*)(o + lane * 4) = r4;
}

// ---------------- launch ----------------
extern "C" void kernel_launch(void* const* d_in, const int* in_sizes, int n_in,
                              void* d_out, int out_size) {
    const float* x_user  = (const float*)d_in[0];
    const float* x_item  = (const float*)d_in[1];
    const float* t_user  = (const float*)d_in[2];
    const float* t_item  = (const float*)d_in[3];
    const int*   eui     = (const int*)d_in[4];
    const int*   eiu     = (const int*)d_in[5];
    const float* Wq      = (const float*)d_in[6];
    const float* bq      = (const float*)d_in[7];
    const float* Wk      = (const float*)d_in[8];
    const float* bk      = (const float*)d_in[9];
    const float* Wv      = (const float*)d_in[10];
    const float* bv      = (const float*)d_in[11];
    const float* Wo      = (const float*)d_in[12];
    const float* bo      = (const float*)d_in[13];
    const float* hb      = (const float*)d_in[14];
    const float* beta    = (const float*)d_in[15];
    const float* tau_raw = (const float*)d_in[16];
    const float* gammaP  = (const float*)d_in[17];
    const float* deltaP  = (const float*)d_in[18];
    float* out = (float*)d_out;

    float *proj, *agg;
    cudaGetSymbolAddress((void**)&proj, g_proj);
    cudaGetSymbolAddress((void**)&agg, g_agg);

    cudaFuncSetAttribute(gemm_tf32_kernel,
                         cudaFuncAttributeMaxDynamicSharedMemorySize, GSM_BYTES);

    clear_kernel<<<512, 256>>>();
    build_ht_kernel<<<(2 * E + 255) / 256, 256>>>(eui, eiu);
    scan_kernel<<<2, 1024>>>();
    scatter_kernel<<<(2 * E + 255) / 256, 256>>>(eui, eiu, t_user, t_item,
                                                 hb, beta, tau_raw, gammaP, deltaP);

    int gblocks = (NN + 127) / 128;   // 313

    GemmJobs6 qkv;
    qkv.j[0] = { x_user, Wq, bq, proj + (size_t)0 * NN * C };
    qkv.j[1] = { x_user, Wk, bk, proj + (size_t)1 * NN * C };
    qkv.j[2] = { x_user, Wv, bv, proj + (size_t)2 * NN * C };
    qkv.j[3] = { x_item, Wq, bq, proj + (size_t)3 * NN * C };
    qkv.j[4] = { x_item, Wk, bk, proj + (size_t)4 * NN * C };
    qkv.j[5] = { x_item, Wv, bv, proj + (size_t)5 * NN * C };
    gemm_tf32_kernel<<<dim3(gblocks, 6), 256, GSM_BYTES>>>(qkv, NN);

    dim3 agrid((NN * 32 + 255) / 256, 2);
    attn_kernel<<<agrid, 256>>>();

    // relation 0 (user->item) feeds out_item; relation 1 feeds out_user
    GemmJobs6 ojobs;
    ojobs.j[0] = { agg + (size_t)0 * NN * C, Wo, nullptr, out + (size_t)NN * C };
    ojobs.j[1] = { agg + (size_t)1 * NN * C, Wo, nullptr, out };
    ojobs.j[2] = ojobs.j[0]; ojobs.j[3] = ojobs.j[0];
    ojobs.j[4] = ojobs.j[0]; ojobs.j[5] = ojobs.j[0];
    gemm_tf32_kernel<<<dim3(gblocks, 2), 256, GSM_BYTES>>>(ojobs, NN);

    dim3 fgrid((NN * 32 + 255) / 256, 2);
    final_kernel<<<fgrid, 256>>>(x_user, x_item, bo, out);
}

// round 8
// speedup vs baseline: 3.1115x; 1.3143x over previous
#include <cuda_runtime.h>
#include <cuda_bf16.h>
#include <cstdint>
#include <math.h>

#define NU 40000
#define NI 40000
#define NN 40000
#define C 128
#define H 4
#define HD 32
#define E 200000
#define HSIZE (1 << 19)
#define HMASK (HSIZE - 1)

// ---------------- device scratch (static, no allocs) ----------------
__device__ int   g_ht_keys[4 * HSIZE];
__device__ int   g_ht_cnt [4 * HSIZE];
__device__ float g_proj[6 * NN * C];     // 0:Qu 1:Ku 2:Vu 3:Qi 4:Ki 5:Vi
__device__ float g_agg [2 * NN * C];     // weighted-V aggregate per relation
__device__ int g_cnt_su[NN], g_cnt_du[NN], g_cnt_si[NN], g_cnt_di[NN];
__device__ int g_off0[NN], g_off1[NN];   // CSR offsets (rel0 dst=item, rel1 dst=user)
__device__ int g_cur0[NN], g_cur1[NN];   // scatter cursors
__device__ int    g_src_s[2 * E];        // CSR-sorted source ids
__device__ float4 g_bias4[2 * E];        // per-edge per-head score bias (precomputed)

// ---------------- helpers ----------------
__device__ __forceinline__ unsigned hash_key(int key) {
    unsigned h = (unsigned)key * 2654435761u;
    h ^= h >> 15;
    return h & HMASK;
}

__device__ __forceinline__ void ht_insert(int t, int key) {
    unsigned slot = hash_key(key);
    int* keys = g_ht_keys + t * HSIZE;
    int* cnts = g_ht_cnt + t * HSIZE;
    while (true) {
        int k = keys[slot];
        if (k == key) { atomicAdd(&cnts[slot], 1); return; }
        if (k == -1) {
            int old = atomicCAS(&keys[slot], -1, key);
            if (old == -1 || old == key) { atomicAdd(&cnts[slot], 1); return; }
        }
        slot = (slot + 1) & HMASK;
    }
}

__device__ __forceinline__ int ht_query(int t, int key) {
    unsigned slot = hash_key(key);
    const int* keys = g_ht_keys + t * HSIZE;
    const int* cnts = g_ht_cnt + t * HSIZE;
    while (true) {
        int k = keys[slot];
        if (k == key) return cnts[slot];
        if (k == -1) return 0;
        slot = (slot + 1) & HMASK;
    }
}

__device__ __forceinline__ void ldsm4(uint32_t& r0, uint32_t& r1, uint32_t& r2, uint32_t& r3,
                                      uint32_t addr) {
    asm volatile("ldmatrix.sync.aligned.m8n8.x4.shared.b16 {%0,%1,%2,%3}, [%4];"
                 : "=r"(r0), "=r"(r1), "=r"(r2), "=r"(r3) : "r"(addr));
}

__device__ __forceinline__ void mma_bf16(float* c, const uint32_t* a, const uint32_t* b) {
    asm volatile(
        "mma.sync.aligned.m16n8k16.row.col.f32.bf16.bf16.f32 "
        "{%0,%1,%2,%3}, {%4,%5,%6,%7}, {%8,%9}, {%0,%1,%2,%3};"
        : "+f"(c[0]), "+f"(c[1]), "+f"(c[2]), "+f"(c[3])
        : "r"(a[0]), "r"(a[1]), "r"(a[2]), "r"(a[3]), "r"(b[0]), "r"(b[1]));
}

// ---------------- kernels ----------------
__global__ void clear_kernel() {
    int gid = blockIdx.x * blockDim.x + threadIdx.x;
    int T = gridDim.x * blockDim.x;
    for (int i = gid; i < 4 * HSIZE; i += T) { g_ht_keys[i] = -1; g_ht_cnt[i] = 0; }
    for (int i = gid; i < NN; i += T) {
        g_cnt_su[i] = 0; g_cnt_du[i] = 0; g_cnt_si[i] = 0; g_cnt_di[i] = 0;
        g_cur0[i] = 0; g_cur1[i] = 0;
    }
}

__global__ void build_ht_kernel(const int* __restrict__ eui, const int* __restrict__ eiu) {
    int e = blockIdx.x * blockDim.x + threadIdx.x;
    if (e >= 2 * E) return;
    if (e < E) {
        int su = eui[e], du = eui[e + E];
        ht_insert(0, su * NI + du);      // pid_ui multiset
        ht_insert(3, du * NU + su);      // rev pairs for iu relation
        atomicAdd(&g_cnt_su[su], 1);
        atomicAdd(&g_cnt_du[du], 1);
    } else {
        int i = e - E;
        int si = eiu[i], di = eiu[i + E];
        ht_insert(1, si * NU + di);      // pid_iu multiset
        ht_insert(2, di * NI + si);      // rev pairs for ui relation
        atomicAdd(&g_cnt_si[si], 1);
        atomicAdd(&g_cnt_di[di], 1);
    }
}

// exclusive prefix scan of per-dst degree -> CSR offsets. one block per relation.
__global__ __launch_bounds__(1024) void scan_kernel() {
    int which = blockIdx.x;
    const int* cnt = which ? g_cnt_di : g_cnt_du;
    int* off = which ? g_off1 : g_off0;
    __shared__ int wsum[32];
    __shared__ int carry;
    int tid = threadIdx.x, lane = tid & 31, wid = tid >> 5;
    if (tid == 0) carry = 0;
    __syncthreads();
    for (int base = 0; base < NN; base += 1024) {
        int i = base + tid;
        int v = (i < NN) ? cnt[i] : 0;
        int x = v;
        #pragma unroll
        for (int d = 1; d < 32; d <<= 1) {
            int y = __shfl_up_sync(0xffffffffu, x, d);
            if (lane >= d) x += y;
        }
        if (lane == 31) wsum[wid] = x;
        __syncthreads();
        if (wid == 0) {
            int s = wsum[lane];
            #pragma unroll
            for (int d = 1; d < 32; d <<= 1) {
                int y = __shfl_up_sync(0xffffffffu, s, d);
                if (lane >= d) s += y;
            }
            wsum[lane] = s;   // inclusive across warps
        }
        __syncthreads();
        int wprefix = (wid == 0) ? 0 : wsum[wid - 1];
        int excl = carry + wprefix + (x - v);
        if (i < NN) off[i] = excl;
        __syncthreads();
        if (tid == 0) carry += wsum[31];
        __syncthreads();
    }
}

// scatter edges into CSR order + precompute per-edge head bias float4
__global__ void scatter_kernel(const int* __restrict__ eui, const int* __restrict__ eiu,
                               const float* __restrict__ t_user, const float* __restrict__ t_item,
                               const float* __restrict__ hb, const float* __restrict__ beta,
                               const float* __restrict__ tau_raw,
                               const float* __restrict__ gamma, const float* __restrict__ delta) {
    int idx = blockIdx.x * blockDim.x + threadIdx.x;
    if (idx >= 2 * E) return;
    int r = (idx >= E) ? 1 : 0;
    int e = idx - r * E;
    const int* ei = r ? eiu : eui;
    int src = ei[e], dst = ei[e + E];
    int* cur = r ? g_cur1 : g_cur0;
    const int* off = r ? g_off1 : g_off0;
    int pos = off[dst] + atomicAdd(&cur[dst], 1);
    g_src_s[r * E + pos] = src;

    float ts = (r ? t_item : t_user)[src];
    float td = (r ? t_user : t_item)[dst];
    float dt = fabsf(td - ts) + 1e-6f;
    int pid = src * 40000 + dst;
    float cntf = (float)(ht_query(r, pid) - 1);
    float recf = (ht_query(2 + r, pid) > 0) ? 1.f : 0.f;
    float tau = log1pf(expf(tau_raw[r])) + 1e-6f;
    float a = -log1pf(dt / tau);
    float b = log1pf(cntf);
    float4 bias;
    bias.x = hb[r * H + 0] + a * beta[r * H + 0] + b * gamma[r * H + 0] + recf * delta[r * H + 0];
    bias.y = hb[r * H + 1] + a * beta[r * H + 1] + b * gamma[r * H + 1] + recf * delta[r * H + 1];
    bias.z = hb[r * H + 2] + a * beta[r * H + 2] + b * gamma[r * H + 2] + recf * delta[r * H + 2];
    bias.w = hb[r * H + 3] + a * beta[r * H + 3] + b * gamma[r * H + 3] + recf * delta[r * H + 3];
    g_bias4[r * E + pos] = bias;
}

// fused edge attention: warp per destination, online softmax + weighted-V accumulate.
__global__ __launch_bounds__(256) void attn_kernel() {
    int n = (blockIdx.x * blockDim.x + threadIdx.x) >> 5;
    int lane = threadIdx.x & 31;
    int r = blockIdx.y;
    if (n >= NN) return;

    const float* Q     = g_proj + (size_t)(r == 0 ? 3 : 0) * NN * C + (size_t)n * C;
    const float* Kbase = g_proj + (size_t)(r == 0 ? 1 : 4) * NN * C;
    const float* Vbase = g_proj + (size_t)(r == 0 ? 2 : 5) * NN * C;
    const int* off = r ? g_off1 : g_off0;
    int s0 = off[n];
    int s1 = (n + 1 < NN) ? off[n + 1] : E;

    float4 q = *(const float4*)(Q + lane * 4);
    int h = lane >> 3;

    float m = -INFINITY, z = 0.f;
    float a0 = 0.f, a1 = 0.f, a2 = 0.f, a3 = 0.f;

    for (int j = s0; j < s1; j++) {
        int src = g_src_s[r * E + j];
        const float4 k = *(const float4*)(Kbase + (size_t)src * C + lane * 4);
        float p = q.x * k.x + q.y * k.y + q.z * k.z + q.w * k.w;
        p += __shfl_xor_sync(0xffffffffu, p, 1);
        p += __shfl_xor_sync(0xffffffffu, p, 2);
        p += __shfl_xor_sync(0xffffffffu, p, 4);   // 8-lane group = this head's dot

        float4 bias = g_bias4[r * E + j];
        float bh = (h == 0) ? bias.x : (h == 1) ? bias.y : (h == 2) ? bias.z : bias.w;
        float s = p * 0.1767766952966369f + bh;

        float mn = fmaxf(m, s);
        float fac = __expf(m - mn);     // first iter: exp(-inf) = 0
        float es  = __expf(s - mn);
        z = z * fac + es;
        const float4 v = *(const float4*)(Vbase + (size_t)src * C + lane * 4);
        a0 = a0 * fac + es * v.x;
        a1 = a1 * fac + es * v.y;
        a2 = a2 * fac + es * v.z;
        a3 = a3 * fac + es * v.w;
        m = mn;
    }

    float inv = (z > 0.f) ? 1.f / z : 0.f;
    float* ag = g_agg + (size_t)r * NN * C + (size_t)n * C + lane * 4;
    *(float4*)ag = make_float4(a0 * inv, a1 * inv, a2 * inv, a3 * inv);
}

// ------------- bf16 tensor-core GEMM: C[m][n] = sum_k A[m][k]*W[n][k] (+b[n]) -------------
struct GemmJob { const float* A; const float* W; const float* bias; float* out; };
struct GemmJobs6 { GemmJob j[6]; };

#define BSM_STRIDE 136   // bf16 elems per row: 17 x 16B -> ldmatrix conflict-free
#define BSM_BYTES (2 * 128 * BSM_STRIDE * 2)   // 69632 B

__global__ __launch_bounds__(256) void gemm_bf16_kernel(GemmJobs6 jobs, int M) {
    const GemmJob jb = jobs.j[blockIdx.y];
    extern __shared__ __nv_bfloat16 shb[];
    __nv_bfloat16* As = shb;                      // [128][136] row-major (m, k)
    __nv_bfloat16* Ws = shb + 128 * BSM_STRIDE;   // [128][136] row-major (n, k)
    int tid = threadIdx.x;
    int row0 = blockIdx.x * 128;

    // global fp32 -> smem bf16 (single conversion)
    for (int i = tid; i < 128 * 32; i += 256) {
        int r = i >> 5, c4 = (i & 31) << 2;
        float4 v = make_float4(0.f, 0.f, 0.f, 0.f);
        if (row0 + r < M) v = *(const float4*)(jb.A + (size_t)(row0 + r) * 128 + c4);
        *(__nv_bfloat162*)(As + r * BSM_STRIDE + c4)     = __float22bfloat162_rn(make_float2(v.x, v.y));
        *(__nv_bfloat162*)(As + r * BSM_STRIDE + c4 + 2) = __float22bfloat162_rn(make_float2(v.z, v.w));
        float4 w = *(const float4*)(jb.W + r * 128 + c4);
        *(__nv_bfloat162*)(Ws + r * BSM_STRIDE + c4)     = __float22bfloat162_rn(make_float2(w.x, w.y));
        *(__nv_bfloat162*)(Ws + r * BSM_STRIDE + c4 + 2) = __float22bfloat162_rn(make_float2(w.z, w.w));
    }
    __syncthreads();

    int warp = tid >> 5, lane = tid & 31;
    int wm = warp >> 1, wn = warp & 1;      // warp tile: 32(M) x 64(N)
    int g = lane >> 2, t4 = lane & 3;

    // ldmatrix source addresses (byte offsets into shared space)
    uint32_t sA = (uint32_t)__cvta_generic_to_shared(As);
    uint32_t sW = (uint32_t)__cvta_generic_to_shared(Ws);
    uint32_t aAddr[2], bAddr[4];
    #pragma unroll
    for (int mt = 0; mt < 2; mt++) {
        int row = wm * 32 + mt * 16 + (lane & 15);
        int col = (lane >> 4) << 3;
        aAddr[mt] = sA + (row * BSM_STRIDE + col) * 2;
    }
    #pragma unroll
    for (int ntp = 0; ntp < 4; ntp++) {
        int row = wn * 64 + ntp * 16 + ((lane >> 4) << 3) + (lane & 7);
        int col = ((lane >> 3) & 1) << 3;
        bAddr[ntp] = sW + (row * BSM_STRIDE + col) * 2;
    }

    float acc[2][8][4];
    #pragma unroll
    for (int mt = 0; mt < 2; mt++)
        #pragma unroll
        for (int nt = 0; nt < 8; nt++)
            #pragma unroll
            for (int q = 0; q < 4; q++) acc[mt][nt][q] = 0.f;

    #pragma unroll
    for (int ks = 0; ks < 8; ks++) {
        uint32_t koff = ks * 32;   // 16 bf16 = 32 bytes
        uint32_t a[2][4], b[8][2];
        ldsm4(a[0][0], a[0][1], a[0][2], a[0][3], aAddr[0] + koff);
        ldsm4(a[1][0], a[1][1], a[1][2], a[1][3], aAddr[1] + koff);
        #pragma unroll
        for (int ntp = 0; ntp < 4; ntp++)
            ldsm4(b[2 * ntp][0], b[2 * ntp][1], b[2 * ntp + 1][0], b[2 * ntp + 1][1],
                  bAddr[ntp] + koff);
        #pragma unroll
        for (int mt = 0; mt < 2; mt++)
            #pragma unroll
            for (int nt = 0; nt < 8; nt++)
                mma_bf16(acc[mt][nt], a[mt], b[nt]);
    }

    // epilogue: c0,c1 -> row g, cols 2*t4,2*t4+1 ; c2,c3 -> row g+8
    #pragma unroll
    for (int mt = 0; mt < 2; mt++) {
        #pragma unroll
        for (int half = 0; half < 2; half++) {
            int row = row0 + wm * 32 + mt * 16 + g + half * 8;
            if (row >= M) continue;
            float* orow = jb.out + (size_t)row * 128 + wn * 64;
            #pragma unroll
            for (int nt = 0; nt < 8; nt++) {
                int col = nt * 8 + t4 * 2;
                float b0 = 0.f, b1 = 0.f;
                if (jb.bias) {
                    b0 = jb.bias[wn * 64 + col];
                    b1 = jb.bias[wn * 64 + col + 1];
                }
                float2 o = make_float2(acc[mt][nt][half * 2 + 0] + b0,
                                       acc[mt][nt][half * 2 + 1] + b1);
                *(float2*)(orow + col) = o;
            }
        }
    }
}

// final: out = LayerNorm(proj + indeg*bo + deg + x). one warp per node.
__global__ void final_kernel(const float* __restrict__ x_user, const float* __restrict__ x_item,
                             const float* __restrict__ bo, float* __restrict__ out) {
    int n = (blockIdx.x * blockDim.x + threadIdx.x) >> 5;
    int lane = threadIdx.x & 31;
    int ty = blockIdx.y;     // 0 = user, 1 = item
    if (n >= NN) return;
    float* o = out + (ty == 0 ? (size_t)0 : (size_t)NN * C) + (size_t)n * C;
    const float* x = (ty == 0 ? x_user : x_item) + (size_t)n * C;
    float indeg = (float)(ty == 0 ? g_cnt_di[n] : g_cnt_du[n]);
    float deg = (float)(ty == 0 ? (g_cnt_su[n] + g_cnt_di[n])
                                : (g_cnt_du[n] + g_cnt_si[n]));
    float4 v  = *(float4*)(o + lane * 4);
    float4 xv = *(const float4*)(x + lane * 4);
    float4 bv = *(const float4*)(bo + lane * 4);
    v.x += xv.x + indeg * bv.x + deg;
    v.y += xv.y + indeg * bv.y + deg;
    v.z += xv.z + indeg * bv.z + deg;
    v.w += xv.w + indeg * bv.w + deg;
    float s = v.x + v.y + v.z + v.w;
    #pragma unroll
    for (int d = 16; d; d >>= 1) s += __shfl_xor_sync(0xffffffffu, s, d);
    float mu = s * (1.f / 128.f);
    float d0 = v.x - mu, d1 = v.y - mu, d2 = v.z - mu, d3 = v.w - mu;
    float q = d0 * d0 + d1 * d1 + d2 * d2 + d3 * d3;
    #pragma unroll
    for (int d = 16; d; d >>= 1) q += __shfl_xor_sync(0xffffffffu, q, d);
    float inv = 1.f / sqrtf(q * (1.f / 128.f) + 1e-5f);
    float4 r4 = make_float4(d0 * inv, d1 * inv, d2 * inv, d3 * inv);
    *(float4*)(o + lane * 4) = r4;
}

// ---------------- launch ----------------
extern "C" void kernel_launch(void* const* d_in, const int* in_sizes, int n_in,
                              void* d_out, int out_size) {
    const float* x_user  = (const float*)d_in[0];
    const float* x_item  = (const float*)d_in[1];
    const float* t_user  = (const float*)d_in[2];
    const float* t_item  = (const float*)d_in[3];
    const int*   eui     = (const int*)d_in[4];
    const int*   eiu     = (const int*)d_in[5];
    const float* Wq      = (const float*)d_in[6];
    const float* bq      = (const float*)d_in[7];
    const float* Wk      = (const float*)d_in[8];
    const float* bk      = (const float*)d_in[9];
    const float* Wv      = (const float*)d_in[10];
    const float* bv      = (const float*)d_in[11];
    const float* Wo      = (const float*)d_in[12];
    const float* bo      = (const float*)d_in[13];
    const float* hb      = (const float*)d_in[14];
    const float* beta    = (const float*)d_in[15];
    const float* tau_raw = (const float*)d_in[16];
    const float* gammaP  = (const float*)d_in[17];
    const float* deltaP  = (const float*)d_in[18];
    float* out = (float*)d_out;

    float *proj, *agg;
    cudaGetSymbolAddress((void**)&proj, g_proj);
    cudaGetSymbolAddress((void**)&agg, g_agg);

    cudaFuncSetAttribute(gemm_bf16_kernel,
                         cudaFuncAttributeMaxDynamicSharedMemorySize, BSM_BYTES);

    clear_kernel<<<512, 256>>>();
    build_ht_kernel<<<(2 * E + 255) / 256, 256>>>(eui, eiu);
    scan_kernel<<<2, 1024>>>();

    int gblocks = (NN + 127) / 128;   // 313

    // launch #4 (profiled): QKV GEMMs
    GemmJobs6 qkv;
    qkv.j[0] = { x_user, Wq, bq, proj + (size_t)0 * NN * C };
    qkv.j[1] = { x_user, Wk, bk, proj + (size_t)1 * NN * C };
    qkv.j[2] = { x_user, Wv, bv, proj + (size_t)2 * NN * C };
    qkv.j[3] = { x_item, Wq, bq, proj + (size_t)3 * NN * C };
    qkv.j[4] = { x_item, Wk, bk, proj + (size_t)4 * NN * C };
    qkv.j[5] = { x_item, Wv, bv, proj + (size_t)5 * NN * C };
    gemm_bf16_kernel<<<dim3(gblocks, 6), 256, BSM_BYTES>>>(qkv, NN);

    scatter_kernel<<<(2 * E + 255) / 256, 256>>>(eui, eiu, t_user, t_item,
                                                 hb, beta, tau_raw, gammaP, deltaP);

    dim3 agrid((NN * 32 + 255) / 256, 2);
    attn_kernel<<<agrid, 256>>>();

    // relation 0 (user->item) feeds out_item; relation 1 feeds out_user
    GemmJobs6 ojobs;
    ojobs.j[0] = { agg + (size_t)0 * NN * C, Wo, nullptr, out + (size_t)NN * C };
    ojobs.j[1] = { agg + (size_t)1 * NN * C, Wo, nullptr, out };
    ojobs.j[2] = ojobs.j[0]; ojobs.j[3] = ojobs.j[0];
    ojobs.j[4] = ojobs.j[0]; ojobs.j[5] = ojobs.j[0];
    gemm_bf16_kernel<<<dim3(gblocks, 2), 256, BSM_BYTES>>>(ojobs, NN);

    dim3 fgrid((NN * 32 + 255) / 256, 2);
    final_kernel<<<fgrid, 256>>>(x_user, x_item, bo, out);
}